// round 3
// baseline (speedup 1.0000x reference)
#include <cuda_runtime.h>

// Problem constants
#define HB   4
#define CDIM 64
#define C2   256
#define HFD  128
#define HH   256
#define WW   256

// ---------------------------------------------------------------------------
// Scratch (device globals: allocation-free rule)
// ---------------------------------------------------------------------------
__device__ float g_hmid[HB * C2 * HH * WW];   // 256 MiB intermediate (after spectral step)
__device__ float g_kt[64 * C2];               // circular-conv taps, tap-major [tap][c]

// ---------------------------------------------------------------------------
// f32x2 packed helpers (Blackwell FFMA2: 2x fp32 throughput)
// ---------------------------------------------------------------------------
__device__ __forceinline__ unsigned long long pk2(float lo, float hi) {
    unsigned long long r;
    asm("mov.b64 %0, {%1,%2};" : "=l"(r) : "f"(lo), "f"(hi));
    return r;
}
__device__ __forceinline__ void upk2(unsigned long long v, float& lo, float& hi) {
    asm("mov.b64 {%0,%1}, %2;" : "=f"(lo), "=f"(hi) : "l"(v));
}
__device__ __forceinline__ unsigned long long ffma2(unsigned long long a,
                                                    unsigned long long b,
                                                    unsigned long long c) {
    unsigned long long d;
    asm("fma.rn.f32x2 %0, %1, %2, %3;" : "=l"(d) : "l"(a), "l"(b), "l"(c));
    return d;
}

// ---------------------------------------------------------------------------
// K0: k_c = irfft2(F_c)  (8x5 real spectrum -> 8x8 real spatial taps)
// numpy semantics: ifft along axis -2 (full, e^{+i}), then c2r along axis -1
// (Hermitian ext; Im of DC/Nyquist bins ignored). Total scale 1/64.
// ---------------------------------------------------------------------------
__global__ void k_prep(const float* __restrict__ filt) {
    const int c = threadIdx.x;
    const float R2 = 0.70710678118654752f;
    const float CT[8] = {1.f,  R2, 0.f, -R2, -1.f, -R2,  0.f,  R2};
    const float ST[8] = {0.f,  R2, 1.f,  R2,  0.f, -R2, -1.f, -R2};

    float F[8][5];
    #pragma unroll
    for (int u = 0; u < 8; ++u)
        #pragma unroll
        for (int v = 0; v < 5; ++v)
            F[u][v] = filt[c * 40 + u * 5 + v];

    #pragma unroll
    for (int p = 0; p < 8; ++p) {
        float gr[5], gi[5];
        #pragma unroll
        for (int v = 0; v < 5; ++v) { gr[v] = 0.f; gi[v] = 0.f; }
        #pragma unroll
        for (int u = 0; u < 8; ++u) {
            float cc = CT[(u * p) & 7], ss = ST[(u * p) & 7];
            #pragma unroll
            for (int v = 0; v < 5; ++v) {
                gr[v] = fmaf(F[u][v], cc, gr[v]);
                gi[v] = fmaf(F[u][v], ss, gi[v]);
            }
        }
        #pragma unroll
        for (int q = 0; q < 8; ++q) {
            float val = gr[0] + ((q & 1) ? -gr[4] : gr[4]);
            #pragma unroll
            for (int v = 1; v <= 3; ++v)
                val += 2.f * (gr[v] * CT[(v * q) & 7] - gi[v] * ST[(v * q) & 7]);
            g_kt[(p * 8 + q) * C2 + c] = val * (1.f / 64.f);
        }
    }
}

// ---------------------------------------------------------------------------
// K1: per-patch fused  h = W_in x  (f32x2 packed)  +  8x8 circular conv.
// One block = one 8x8 patch; thread c owns channel c entirely in registers.
// smem: [64][257] W_in^T | [64][64] x patch | [64][257] output stage
// ---------------------------------------------------------------------------
#define K1_SMEM ((64 * 257 + 64 * 64 + 64 * 257) * 4)

__global__ __launch_bounds__(256) void k_proj_spec(const float* __restrict__ x,
                                                   const float* __restrict__ w_in) {
    extern __shared__ float smem[];
    float* sw  = smem;               // [d][c], stride 257 (bank-conflict-free)
    float* sx  = sw + 64 * 257;      // [d][px]
    float* syb = sx + 64 * 64;       // [px][c], stride 257

    const int t  = threadIdx.x;
    const int pi = blockIdx.x;
    const int b  = pi >> 10;
    const int rr = pi & 1023;
    const int pr = rr >> 5, pc = rr & 31;

    // stage W_in transposed ([c][d] global -> [d][c] smem)
    for (int k = 0; k < 64; ++k) {
        int e  = t + k * 256;
        int cc = e >> 6, dd = e & 63;
        sw[dd * 257 + cc] = w_in[e];
    }
    // stage x patch (64 input channels x 64 px)
    {
        int xbase = b * (CDIM * HH * WW) + (pr * 8) * WW + pc * 8;
        for (int k = 0; k < 16; ++k) {
            int e  = t + k * 256;
            int dd = e >> 6, px = e & 63;
            sx[e] = x[xbase + dd * (HH * WW) + (px >> 3) * WW + (px & 7)];
        }
    }
    __syncthreads();

    const int c = t;

    // Phase 1: projection with packed f32x2 FMA; h (64 px) in 32 b64 regs
    unsigned long long h2[32];
    #pragma unroll
    for (int j = 0; j < 32; ++j) h2[j] = 0ULL;
    for (int d = 0; d < 64; ++d) {
        float w = sw[d * 257 + c];
        unsigned long long w2 = pk2(w, w);
        const unsigned long long* xr =
            reinterpret_cast<const unsigned long long*>(sx + d * 64);
        #pragma unroll
        for (int j = 0; j < 32; ++j)
            h2[j] = ffma2(w2, xr[j], h2[j]);
    }
    float hs[64];
    #pragma unroll
    for (int j = 0; j < 32; ++j) upk2(h2[j], hs[2 * j], hs[2 * j + 1]);

    // taps for this channel (tap-major global: coalesced, L2-resident)
    float kk[64];
    #pragma unroll
    for (int tp = 0; tp < 64; ++tp) kk[tp] = g_kt[tp * C2 + c];

    // Phase 2: 8x8 circular convolution, fully unrolled (constant reg indices)
    #pragma unroll
    for (int p = 0; p < 8; ++p) {
        #pragma unroll
        for (int q = 0; q < 8; ++q) {
            float acc = 0.f;
            #pragma unroll
            for (int u = 0; u < 8; ++u) {
                #pragma unroll
                for (int v = 0; v < 8; ++v)
                    acc = fmaf(hs[u * 8 + v],
                               kk[((p - u) & 7) * 8 + ((q - v) & 7)], acc);
            }
            syb[(p * 8 + q) * 257 + c] = acc;
        }
    }
    __syncthreads();

    // cooperative coalesced store (32B-sector aligned rows of 8)
    int obase = b * (C2 * HH * WW) + (pr * 8) * WW + pc * 8;
    for (int k = 0; k < 64; ++k) {
        int e  = t + k * 256;
        int cc = e >> 6, px = e & 63;
        g_hmid[obase + cc * (HH * WW) + (px >> 3) * WW + (px & 7)] =
            syb[px * 257 + cc];
    }
}

// ---------------------------------------------------------------------------
// K2: depthwise 3x3 (SAME) + exact GELU gate + W_out projection.
// One block = 16x16 output tile; 64 output-channel accumulators per thread
// (f32x2 packed). smem-staged transpose for coalesced final stores.
// ---------------------------------------------------------------------------
#define K2_SMEM ((128 * 66 + 2304 + 2 * 324 + 256 * 65) * 4)

__global__ __launch_bounds__(256) void k_dw_out(const float* __restrict__ w_dw,
                                                const float* __restrict__ w_out,
                                                float* __restrict__ out) {
    extern __shared__ float smem[];
    float* swo  = smem;                 // [c][o] w_out^T, stride 66 (8B aligned pairs)
    float* sdw  = swo + 128 * 66;       // [256*9] depthwise weights
    float* st1  = sdw + 2304;           // [18*18] tile+halo, channel c
    float* st2  = st1 + 324;            // [18*18] tile+halo, channel c+128
    float* sout = st2 + 324;            // [px][o], stride 65

    const int t  = threadIdx.x;
    const int b  = blockIdx.z;
    const int x0 = blockIdx.x * 16, y0 = blockIdx.y * 16;
    const int yl = t >> 4, xl = t & 15;

    for (int k = 0; k < 32; ++k) {
        int e = t + k * 256;
        int o = e >> 7, cc = e & 127;
        swo[cc * 66 + o] = w_out[e];    // w_out[o][cc] -> swo[cc][o]
    }
    for (int e = t; e < 2304; e += 256) sdw[e] = w_dw[e];

    unsigned long long acc2[32];
    #pragma unroll
    for (int j = 0; j < 32; ++j) acc2[j] = 0ULL;

    for (int c = 0; c < 128; ++c) {
        __syncthreads();                 // protect previous tile + (c==0) swo/sdw
        int base1 = (b * C2 + c) << 16;
        int base2 = (b * C2 + c + 128) << 16;
        for (int i = t; i < 324; i += 256) {
            int r  = i / 18, cc = i - r * 18;
            int gy = y0 - 1 + r, gx = x0 - 1 + cc;
            bool ok = (gy >= 0) & (gy < 256) & (gx >= 0) & (gx < 256);
            int gidx = gy * 256 + gx;
            st1[i] = ok ? g_hmid[base1 + gidx] : 0.f;
            st2[i] = ok ? g_hmid[base2 + gidx] : 0.f;
        }
        __syncthreads();

        const float* wd1 = sdw + c * 9;
        const float* wd2 = sdw + (c + 128) * 9;
        float d1 = 0.f, d2 = 0.f;
        #pragma unroll
        for (int i = 0; i < 3; ++i)
            #pragma unroll
            for (int j = 0; j < 3; ++j) {
                d1 = fmaf(st1[(yl + i) * 18 + xl + j], wd1[i * 3 + j], d1);
                d2 = fmaf(st2[(yl + i) * 18 + xl + j], wd2[i * 3 + j], d2);
            }
        // exact GELU gate: gelu(d1) * d2
        float g = 0.5f * d1 * (1.f + erff(d1 * 0.70710678118654752f)) * d2;
        unsigned long long gg = pk2(g, g);
        const unsigned long long* wrow =
            reinterpret_cast<const unsigned long long*>(swo + c * 66);
        #pragma unroll
        for (int j = 0; j < 32; ++j)
            acc2[j] = ffma2(wrow[j], gg, acc2[j]);
    }

    // stage output through smem for coalesced stores
    #pragma unroll
    for (int j = 0; j < 32; ++j) {
        float lo, hi;
        upk2(acc2[j], lo, hi);
        sout[t * 65 + 2 * j]     = lo;
        sout[t * 65 + 2 * j + 1] = hi;
    }
    __syncthreads();
    for (int k = 0; k < 64; ++k) {
        int e  = t + k * 256;
        int o  = e >> 8, px = e & 255;
        int oy = px >> 4, ox = px & 15;
        out[((b * 64 + o) << 16) + (y0 + oy) * 256 + x0 + ox] = sout[px * 65 + o];
    }
}

// ---------------------------------------------------------------------------
// launch
// ---------------------------------------------------------------------------
extern "C" void kernel_launch(void* const* d_in, const int* in_sizes, int n_in,
                              void* d_out, int out_size) {
    const float* x     = (const float*)d_in[0];   // (4,64,256,256)
    const float* w_in  = (const float*)d_in[1];   // (256,64)
    const float* w_dw  = (const float*)d_in[2];   // (256,1,3,3)
    const float* filt  = (const float*)d_in[3];   // (256,1,1,8,5)
    const float* w_out = (const float*)d_in[4];   // (64,128)
    float* out = (float*)d_out;                   // (4,64,256,256)

    cudaFuncSetAttribute(k_proj_spec, cudaFuncAttributeMaxDynamicSharedMemorySize, K1_SMEM);
    cudaFuncSetAttribute(k_dw_out,    cudaFuncAttributeMaxDynamicSharedMemorySize, K2_SMEM);

    k_prep<<<1, 256>>>(filt);
    k_proj_spec<<<HB * 32 * 32, 256, K1_SMEM>>>(x, w_in);
    k_dw_out<<<dim3(16, 16, HB), 256, K2_SMEM>>>(w_dw, w_out, out);
}

// round 5
// speedup vs baseline: 1.5400x; 1.5400x over previous
#include <cuda_runtime.h>

// Problem constants
#define HB   4
#define CDIM 64
#define C2   256
#define HFD  128
#define HH   256
#define WW   256

// ---------------------------------------------------------------------------
// Scratch (device globals: allocation-free rule)
// ---------------------------------------------------------------------------
__device__ float g_hmid[HB * C2 * HH * WW];   // 256 MiB intermediate (post-spectral)
__device__ float g_kp[64 * C2 * 2];           // packed circular-conv tap PAIRS:
                                              // pair[r*8+j][c] = (k[r][j], k[r][(j+1)&7])

// ---------------------------------------------------------------------------
// f32x2 packed helpers (Blackwell FFMA2: 2x fp32 throughput)
// ---------------------------------------------------------------------------
__device__ __forceinline__ unsigned long long pk2(float lo, float hi) {
    unsigned long long r;
    asm("mov.b64 %0, {%1,%2};" : "=l"(r) : "f"(lo), "f"(hi));
    return r;
}
__device__ __forceinline__ void upk2(unsigned long long v, float& lo, float& hi) {
    asm("mov.b64 {%0,%1}, %2;" : "=f"(lo), "=f"(hi) : "l"(v));
}
__device__ __forceinline__ unsigned long long ffma2(unsigned long long a,
                                                    unsigned long long b,
                                                    unsigned long long c) {
    unsigned long long d;
    asm("fma.rn.f32x2 %0, %1, %2, %3;" : "=l"(d) : "l"(a), "l"(b), "l"(c));
    return d;
}

// ---------------------------------------------------------------------------
// K0: k_c = irfft2(F_c) (8x5 real spectrum -> 8x8 taps), emit packed pairs.
// ---------------------------------------------------------------------------
__global__ void k_prep(const float* __restrict__ filt) {
    const int c = threadIdx.x;
    const float R2 = 0.70710678118654752f;
    const float CT[8] = {1.f,  R2, 0.f, -R2, -1.f, -R2,  0.f,  R2};
    const float ST[8] = {0.f,  R2, 1.f,  R2,  0.f, -R2, -1.f, -R2};

    float F[8][5];
    #pragma unroll
    for (int u = 0; u < 8; ++u)
        #pragma unroll
        for (int v = 0; v < 5; ++v)
            F[u][v] = filt[c * 40 + u * 5 + v];

    float kv[64];
    #pragma unroll
    for (int p = 0; p < 8; ++p) {
        float gr[5], gi[5];
        #pragma unroll
        for (int v = 0; v < 5; ++v) { gr[v] = 0.f; gi[v] = 0.f; }
        #pragma unroll
        for (int u = 0; u < 8; ++u) {
            float cc = CT[(u * p) & 7], ss = ST[(u * p) & 7];
            #pragma unroll
            for (int v = 0; v < 5; ++v) {
                gr[v] = fmaf(F[u][v], cc, gr[v]);
                gi[v] = fmaf(F[u][v], ss, gi[v]);
            }
        }
        #pragma unroll
        for (int q = 0; q < 8; ++q) {
            float val = gr[0] + ((q & 1) ? -gr[4] : gr[4]);
            #pragma unroll
            for (int v = 1; v <= 3; ++v)
                val += 2.f * (gr[v] * CT[(v * q) & 7] - gi[v] * ST[(v * q) & 7]);
            kv[p * 8 + q] = val * (1.f / 64.f);
        }
    }
    #pragma unroll
    for (int r = 0; r < 8; ++r)
        #pragma unroll
        for (int j = 0; j < 8; ++j) {
            int idx = r * 8 + j;
            g_kp[(idx * C2 + c) * 2]     = kv[r * 8 + j];
            g_kp[(idx * C2 + c) * 2 + 1] = kv[r * 8 + ((j + 1) & 7)];
        }
}

// ---------------------------------------------------------------------------
// K1: per-patch fused  h = W_in x (f32x2)  +  8x8 circular conv (f32x2 scatter).
// One block = one 8x8 patch; thread c owns channel c in registers.
// smem: phase1 [64][257] W_in^T | [64][64] x   -> aliased -> phase2 [64][257] y
// ---------------------------------------------------------------------------
#define K1_SMEM ((64 * 257 + 64 * 64) * 4)

__global__ __launch_bounds__(256) void k_proj_spec(const float* __restrict__ x,
                                                   const float* __restrict__ w_in) {
    extern __shared__ float smem[];
    float* sw  = smem;               // [d][c], stride 257
    float* sx  = sw + 64 * 257;      // [d][px]
    float* syb = smem;               // ALIAS: [px][c], stride 257 (after sync)

    const int t  = threadIdx.x;
    const int pi = blockIdx.x;
    const int b  = pi >> 10;
    const int rr = pi & 1023;
    const int pr = rr >> 5, pc = rr & 31;

    // stage W_in transposed ([c][d] global -> [d][c] smem)
    for (int k = 0; k < 64; ++k) {
        int e  = t + k * 256;
        int cc = e >> 6, dd = e & 63;
        sw[dd * 257 + cc] = w_in[e];
    }
    // stage x patch (64 input channels x 64 px)
    {
        int xbase = b * (CDIM * HH * WW) + (pr * 8) * WW + pc * 8;
        for (int k = 0; k < 16; ++k) {
            int e  = t + k * 256;
            int dd = e >> 6, px = e & 63;
            sx[e] = x[xbase + dd * (HH * WW) + (px >> 3) * WW + (px & 7)];
        }
    }
    __syncthreads();

    const int c = t;

    // Phase 1: projection with packed f32x2 FMA; h (64 px) in 32 b64 regs
    unsigned long long h2[32];
    #pragma unroll
    for (int j = 0; j < 32; ++j) h2[j] = 0ULL;
    for (int d = 0; d < 64; ++d) {
        float w = sw[d * 257 + c];
        unsigned long long w2 = pk2(w, w);
        const unsigned long long* xr =
            reinterpret_cast<const unsigned long long*>(sx + d * 64);
        #pragma unroll
        for (int j = 0; j < 32; ++j)
            h2[j] = ffma2(w2, xr[j], h2[j]);
    }
    float hs[64];
    #pragma unroll
    for (int j = 0; j < 32; ++j) upk2(h2[j], hs[2 * j], hs[2 * j + 1]);

    // packed tap pairs for this channel (coalesced 8B loads, L2-resident)
    unsigned long long kp[64];
    {
        const unsigned long long* gk =
            reinterpret_cast<const unsigned long long*>(g_kp);
        #pragma unroll
        for (int i = 0; i < 64; ++i) kp[i] = gk[i * C2 + c];
    }

    __syncthreads();   // all reads of sw/sx done before syb (alias) writes

    // Phase 2: circular conv, scatter form, output pairs, two half-passes.
    // y[p][2j,2j+1] += h[u][v] * (k[(p-u)&7][(2j-v)&7], k[(p-u)&7][(2j+1-v)&7])
    #pragma unroll
    for (int half = 0; half < 2; ++half) {
        unsigned long long acc2[16];
        #pragma unroll
        for (int i = 0; i < 16; ++i) acc2[i] = 0ULL;
        #pragma unroll
        for (int u = 0; u < 8; ++u) {
            #pragma unroll
            for (int v = 0; v < 8; ++v) {
                float hv = hs[u * 8 + v];
                unsigned long long h2v = pk2(hv, hv);
                #pragma unroll
                for (int p4 = 0; p4 < 4; ++p4) {
                    int r = ((half * 4 + p4) - u) & 7;
                    #pragma unroll
                    for (int j = 0; j < 4; ++j)
                        acc2[p4 * 4 + j] =
                            ffma2(h2v, kp[r * 8 + ((2 * j - v) & 7)], acc2[p4 * 4 + j]);
                }
            }
        }
        #pragma unroll
        for (int p4 = 0; p4 < 4; ++p4)
            #pragma unroll
            for (int j = 0; j < 4; ++j) {
                float lo, hi;
                upk2(acc2[p4 * 4 + j], lo, hi);
                int p = half * 4 + p4;
                syb[(p * 8 + 2 * j) * 257 + c]     = lo;
                syb[(p * 8 + 2 * j + 1) * 257 + c] = hi;
            }
    }
    __syncthreads();

    // cooperative coalesced store
    int obase = b * (C2 * HH * WW) + (pr * 8) * WW + pc * 8;
    for (int k = 0; k < 64; ++k) {
        int e  = t + k * 256;
        int cc = e >> 6, px = e & 63;
        g_hmid[obase + cc * (HH * WW) + (px >> 3) * WW + (px & 7)] =
            syb[px * 257 + cc];
    }
}

// ---------------------------------------------------------------------------
// K2: depthwise 3x3 (SAME) + exact GELU gate + W_out projection.
// Software-pipelined channel loop (ping-pong smem tiles, register prefetch
// 2 channels ahead, 1 barrier/iter). smem aliased for 2 blocks/SM.
// ---------------------------------------------------------------------------
#define K2_SMEM (16640 * 4)   // max(loop phase 12048, out phase 16640) floats

__device__ __forceinline__ void k2_prefetch(int b, int c, int y0, int x0, int t,
                                            float r[3]) {
    #pragma unroll
    for (int s = 0; s < 3; ++s) {
        int i = t + s * 256;
        float v = 0.f;
        if (i < 648) {
            int which = (i >= 324) ? 1 : 0;
            int j  = i - which * 324;
            int rr = j / 18, cc = j - rr * 18;
            int gy = y0 - 1 + rr, gx = x0 - 1 + cc;
            if (gy >= 0 && gy < 256 && gx >= 0 && gx < 256)
                v = g_hmid[((b * C2 + c + which * 128) << 16) + gy * 256 + gx];
        }
        r[s] = v;
    }
}

__global__ __launch_bounds__(256, 2) void k_dw_out(const float* __restrict__ w_dw,
                                                   const float* __restrict__ w_out,
                                                   float* __restrict__ out) {
    extern __shared__ float smem[];
    float* swo   = smem;              // [c][o] w_out^T, stride 66     (8448)
    float* sdw   = smem + 8448;       // [256*9] depthwise weights     (2304)
    float* tiles = smem + 10752;      // 2 buffers x (2ch x 324)       (1296)
    float* sout  = smem;              // ALIAS (out phase): [px][o], stride 65

    const int t  = threadIdx.x;
    const int b  = blockIdx.z;
    const int x0 = blockIdx.x * 16, y0 = blockIdx.y * 16;
    const int yl = t >> 4, xl = t & 15;

    for (int k = 0; k < 32; ++k) {
        int e = t + k * 256;
        int o = e >> 7, cc = e & 127;
        swo[cc * 66 + o] = w_out[e];
    }
    for (int e = t; e < 2304; e += 256) sdw[e] = w_dw[e];

    // prefetch channel 0 -> buf0, channel 1 -> registers
    float rA[3], rN[3];
    k2_prefetch(b, 0, y0, x0, t, rA);
    #pragma unroll
    for (int s = 0; s < 3; ++s) {
        int i = t + s * 256;
        if (i < 648) tiles[i] = rA[s];
    }
    k2_prefetch(b, 1, y0, x0, t, rA);   // rA now holds c=1 data
    __syncthreads();

    unsigned long long acc2[32];
    #pragma unroll
    for (int j = 0; j < 32; ++j) acc2[j] = 0ULL;

    for (int c = 0; c < 128; ++c) {
        float* cur = tiles + (c & 1) * 648;
        float* nxt = tiles + ((c + 1) & 1) * 648;

        // stage c+1 data (readers of nxt finished at iter c-1, synced)
        if (c < 127) {
            #pragma unroll
            for (int s = 0; s < 3; ++s) {
                int i = t + s * 256;
                if (i < 648) nxt[i] = rA[s];
            }
        }
        // issue loads for c+2 (latency hidden behind this iteration)
        if (c < 126) k2_prefetch(b, c + 2, y0, x0, t, rN);

        const float* wd1 = sdw + c * 9;
        const float* wd2 = sdw + (c + 128) * 9;
        float d1 = 0.f, d2 = 0.f;
        #pragma unroll
        for (int i = 0; i < 3; ++i)
            #pragma unroll
            for (int j = 0; j < 3; ++j) {
                d1 = fmaf(cur[(yl + i) * 18 + xl + j],       wd1[i * 3 + j], d1);
                d2 = fmaf(cur[324 + (yl + i) * 18 + xl + j], wd2[i * 3 + j], d2);
            }
        // exact GELU gate
        float g = 0.5f * d1 * (1.f + erff(d1 * 0.70710678118654752f)) * d2;
        unsigned long long gg = pk2(g, g);
        const unsigned long long* wrow =
            reinterpret_cast<const unsigned long long*>(swo + c * 66);
        #pragma unroll
        for (int j = 0; j < 32; ++j)
            acc2[j] = ffma2(wrow[j], gg, acc2[j]);

        __syncthreads();
        rA[0] = rN[0]; rA[1] = rN[1]; rA[2] = rN[2];
    }

    // stage output (sout aliases swo/sdw/tiles — all dead now)
    #pragma unroll
    for (int j = 0; j < 32; ++j) {
        float lo, hi;
        upk2(acc2[j], lo, hi);
        sout[t * 65 + 2 * j]     = lo;
        sout[t * 65 + 2 * j + 1] = hi;
    }
    __syncthreads();
    for (int k = 0; k < 64; ++k) {
        int e  = t + k * 256;
        int o  = e >> 8, px = e & 255;
        int oy = px >> 4, ox = px & 15;
        out[((b * 64 + o) << 16) + (y0 + oy) * 256 + x0 + ox] = sout[px * 65 + o];
    }
}

// ---------------------------------------------------------------------------
// launch
// ---------------------------------------------------------------------------
extern "C" void kernel_launch(void* const* d_in, const int* in_sizes, int n_in,
                              void* d_out, int out_size) {
    const float* x     = (const float*)d_in[0];   // (4,64,256,256)
    const float* w_in  = (const float*)d_in[1];   // (256,64)
    const float* w_dw  = (const float*)d_in[2];   // (256,1,3,3)
    const float* filt  = (const float*)d_in[3];   // (256,1,1,8,5)
    const float* w_out = (const float*)d_in[4];   // (64,128)
    float* out = (float*)d_out;                   // (4,64,256,256)

    cudaFuncSetAttribute(k_proj_spec, cudaFuncAttributeMaxDynamicSharedMemorySize, K1_SMEM);
    cudaFuncSetAttribute(k_dw_out,    cudaFuncAttributeMaxDynamicSharedMemorySize, K2_SMEM);

    k_prep<<<1, 256>>>(filt);
    k_proj_spec<<<HB * 32 * 32, 256, K1_SMEM>>>(x, w_in);
    k_dw_out<<<dim3(16, 16, HB), 256, K2_SMEM>>>(w_dw, w_out, out);
}